// round 15
// baseline (speedup 1.0000x reference)
#include <cuda_runtime.h>
#include <cstdint>

#define KNN 64
#define WPB 16
#define THREADS 512
#define QPB (WPB * 2)            // 32 queries per block
#define POOLCAP 160
#define PCAP2 164                // POOLCAP + 4 pad entries (uint4-aligned)
#define FULLMASK 0xFFFFFFFFu

typedef unsigned long long u64;

// Packed 2xfp32 ops (sm_100+). ptxas never emits these from C++ — PTX only.
// (No packed min/max exists; trackers use scalar IMNMX.)
#define PACK2(out, lo, hi) \
    asm("mov.b64 %0, {%1, %2};" : "=l"(out) : "f"(lo), "f"(hi))
#define ADD2(out, a, b) \
    asm("add.rn.f32x2 %0, %1, %2;" : "=l"(out) : "l"(a), "l"(b))
#define MUL2(out, a, b) \
    asm("mul.rn.f32x2 %0, %1, %2;" : "=l"(out) : "l"(a), "l"(b))
#define FMA2(out, a, b, c) \
    asm("fma.rn.f32x2 %0, %1, %2, %3;" : "=l"(out) : "l"(a), "l"(b), "l"(c))

__device__ __forceinline__ unsigned umin_(unsigned a, unsigned b) { return a < b ? a : b; }
__device__ __forceinline__ unsigned umax_(unsigned a, unsigned b) { return a > b ? a : b; }

// Diff-form packed distance: d2 = (q-c).(q-c), c pre-negated in smem.
// Op order w,z,y,x matches the scalar fallback exactly. d2 >= 0 always.
#define DIST2(dout, CX, CY, CZ, CW, QX, QY, QZ, QW) do {                   \
    u64 _dx, _dy, _dz, _dw;                                                \
    ADD2(_dx, QX, CX); ADD2(_dy, QY, CY);                                  \
    ADD2(_dz, QZ, CZ); ADD2(_dw, QW, CW);                                  \
    MUL2(dout, _dw, _dw); FMA2(dout, _dz, _dz, dout);                      \
    FMA2(dout, _dy, _dy, dout); FMA2(dout, _dx, _dx, dout);                \
} while (0)

// Insert packed pair (v0,v1) into sorted pair-slot (s0 <= s1): 6 IMNMX.
#define INS2(s0, s1, v0, v1) do {                                          \
    unsigned _lo = umin_(v0, v1), _hi = umax_(v0, v1);                     \
    s1 = umin_(umax_(s0, _lo), umin_(s1, _hi));                            \
    s0 = umin_(s0, _lo);                                                   \
} while (0)

// Bisection over 4 collected values/lane: returns hi with
// warp-count(values < hi) >= target (invariant held from the initial hi).
__device__ __forceinline__ unsigned bisect4(unsigned v0, unsigned v1,
                                            unsigned v2, unsigned v3,
                                            unsigned lo, unsigned hi,
                                            unsigned target, int rounds)
{
    for (int it = 0; it < rounds && lo + 1u < hi; ++it) {
        unsigned mid = lo + ((hi - lo) >> 1);
        unsigned c = (unsigned)(v0 < mid) + (unsigned)(v1 < mid)
                   + (unsigned)(v2 < mid) + (unsigned)(v3 < mid);
        c = __reduce_add_sync(FULLMASK, c);
        if (c >= target) hi = mid; else lo = mid;
    }
    return hi;
}

// Exact rank scatter over split pools. Ranks by u32 d2-bits (uint4 inner
// loop); exactness verified by the rank-sum permutation check, with an exact
// (d2, idx) lexicographic re-rank on the (rare) tie.
template <int R>
__device__ __forceinline__ void rank_scatter(const unsigned* pD, const unsigned* pI,
                                             int cnt,
                                             float* out_idx, float* out_dist,
                                             size_t obase, int gbase, int lane)
{
    unsigned kd[R], ki[R];
    int r[R];
#pragma unroll
    for (int i = 0; i < R; i++) {
        int e = lane + 32 * i;
        bool v = e < cnt;
        kd[i] = v ? pD[e] : 0xFFFFFFFFu;
        ki[i] = v ? pI[e] : 0u;
        r[i] = 0;
    }
    const int cntP = (cnt + 3) & ~3;
    for (int j = 0; j < cntP; j += 4) {
        uint4 d = *reinterpret_cast<const uint4*>(pD + j);   // LDS.128 broadcast
#pragma unroll
        for (int i = 0; i < R; i++) {
            r[i] += (int)(d.x < kd[i]) + (int)(d.y < kd[i])
                  + (int)(d.z < kd[i]) + (int)(d.w < kd[i]);
        }
    }
    int s = 0;
#pragma unroll
    for (int i = 0; i < R; i++)
        if (lane + 32 * i < cnt) s += r[i];
    s = __reduce_add_sync(FULLMASK, s);
    if (s != (cnt * (cnt - 1)) / 2) {
#pragma unroll
        for (int i = 0; i < R; i++) r[i] = 0;
        for (int j = 0; j < cnt; j++) {
            unsigned dj = pD[j], ij = pI[j];
#pragma unroll
            for (int i = 0; i < R; i++)
                r[i] += (int)((dj < kd[i]) || (dj == kd[i] && ij < ki[i]));
        }
    }
#pragma unroll
    for (int i = 0; i < R; i++) {
        int e = lane + 32 * i;
        if (e < cnt && r[i] < KNN) {
            out_idx [obase + r[i]] = (float)((int)ki[i] + gbase);
            out_dist[obase + r[i]] = __uint_as_float(kd[i]);
        }
    }
}

// Single-query collect: append all candidates with d2bits < tau.
__device__ __forceinline__ void collect_one(const float* nx, const float* ny,
                                            const float* nz, const float* nw,
                                            u64 qx, u64 qy, u64 qz, u64 qw,
                                            unsigned tau, int iters, int lane4,
                                            unsigned* pD, unsigned* pI, int* cnt)
{
#pragma unroll 2
    for (int m = 0; m < iters; m++) {
        const int j = (m << 7) + lane4;
        ulonglong2 cx = *reinterpret_cast<const ulonglong2*>(nx + j);
        ulonglong2 cy = *reinterpret_cast<const ulonglong2*>(ny + j);
        ulonglong2 cz = *reinterpret_cast<const ulonglong2*>(nz + j);
        ulonglong2 cw = *reinterpret_cast<const ulonglong2*>(nw + j);
        u64 d0, d1;
        DIST2(d0, cx.x, cy.x, cz.x, cw.x, qx, qy, qz, qw);
        DIST2(d1, cx.y, cy.y, cz.y, cw.y, qx, qy, qz, qw);
        unsigned v0 = (unsigned)d0, v1 = (unsigned)(d0 >> 32);
        unsigned v2 = (unsigned)d1, v3 = (unsigned)(d1 >> 32);
        if (v0 < tau) { int p = atomicAdd(cnt, 1);
            if (p < POOLCAP) { pD[p] = v0; pI[p] = (unsigned)(j + 0); } }
        if (v1 < tau) { int p = atomicAdd(cnt, 1);
            if (p < POOLCAP) { pD[p] = v1; pI[p] = (unsigned)(j + 1); } }
        if (v2 < tau) { int p = atomicAdd(cnt, 1);
            if (p < POOLCAP) { pD[p] = v2; pI[p] = (unsigned)(j + 2); } }
        if (v3 < tau) { int p = atomicAdd(cnt, 1);
            if (p < POOLCAP) { pD[p] = v3; pI[p] = (unsigned)(j + 3); } }
    }
    __syncwarp();
}

// Exact repair: full tracker pass -> guaranteed-valid tau -> re-collect.
__device__ __forceinline__ int exact_fix(const float* nx, const float* ny,
                                         const float* nz, const float* nw,
                                         u64 qx, u64 qy, u64 qz, u64 qw,
                                         int iters, int lane4, int lane,
                                         unsigned* pD, unsigned* pI, int* cnt)
{
    unsigned T00 = ~0u, T01 = ~0u, T10 = ~0u, T11 = ~0u;
#pragma unroll 2
    for (int m = 0; m < iters; m++) {
        const int j = (m << 7) + lane4;
        ulonglong2 cx = *reinterpret_cast<const ulonglong2*>(nx + j);
        ulonglong2 cy = *reinterpret_cast<const ulonglong2*>(ny + j);
        ulonglong2 cz = *reinterpret_cast<const ulonglong2*>(nz + j);
        ulonglong2 cw = *reinterpret_cast<const ulonglong2*>(nw + j);
        u64 d0, d1;
        DIST2(d0, cx.x, cy.x, cz.x, cw.x, qx, qy, qz, qw);
        DIST2(d1, cx.y, cy.y, cz.y, cw.y, qx, qy, qz, qw);
        INS2(T00, T01, (unsigned)d0, (unsigned)(d0 >> 32));
        INS2(T10, T11, (unsigned)d1, (unsigned)(d1 >> 32));
    }
    // tau = (>=64th smallest of 128 collected) + eps: upper-bounds true 64th.
    unsigned lo = __reduce_min_sync(FULLMASK, umin_(T00, T10));
    unsigned hi = __reduce_max_sync(FULLMASK, umax_(T01, T11)) + 1u;  // count==128
    unsigned tau = bisect4(T00, T01, T10, T11, lo, hi, 64u, 16);
    if (lane == 0) *cnt = 0;
    __syncwarp();
    collect_one(nx, ny, nz, nw, qx, qy, qz, qw, tau, iters, lane4, pD, pI, cnt);
    return *cnt;
}

// Exact bound-tournament (ultimate fallback; scalar diff-form, same op order).
__device__ __forceinline__ void exact_tournament(const float* nx, const float* ny,
                                                 const float* nz, const float* nw,
                                                 float qx, float qy, float qz, float qw,
                                                 int S,
                                                 float* out_idx, float* out_dist,
                                                 size_t obase, int gbase, int lane)
{
    u64 bound = 0ULL;
    const int iters = S >> 5;
#pragma unroll 1
    for (int kk = 0; kk < KNN; kk++) {
        u64 best = ~0ULL;
        for (int m = 0; m < iters; m++) {
            const int j = (m << 5) + lane;
            float dx = qx + nx[j], dy = qy + ny[j], dz = qz + nz[j], dw = qw + nw[j];
            float d2 = fmaf(dx, dx, fmaf(dy, dy, fmaf(dz, dz, dw * dw)));
            u64 key = (((u64)__float_as_uint(d2)) << 32) | (unsigned)j;
            if (key >= bound && key < best) best = key;
        }
        unsigned hb = (unsigned)(best >> 32);
        unsigned mh = __reduce_min_sync(FULLMASK, hb);
        unsigned lb = (hb == mh) ? (unsigned)best : 0xFFFFFFFFu;
        unsigned ml = __reduce_min_sync(FULLMASK, lb);
        if (lane == 0) {
            out_idx [obase + kk] = (float)((int)ml + gbase);
            out_dist[obase + kk] = __uint_as_float(mh);
        }
        bound = ((((u64)mh) << 32) | ml) + 1ULL;
    }
}

__device__ __forceinline__ void finish_query(const float* nx, const float* ny,
                                             const float* nz, const float* nw,
                                             u64 qx, u64 qy, u64 qz, u64 qw,
                                             float fqx, float fqy, float fqz, float fqw,
                                             int cnt, int iters, int lane4, int lane, int S,
                                             unsigned* pD, unsigned* pI, int* cntp,
                                             float* out_idx, float* out_dist,
                                             size_t obase, int gbase)
{
    if (cnt < KNN || cnt > POOLCAP)
        cnt = exact_fix(nx, ny, nz, nw, qx, qy, qz, qw, iters, lane4, lane,
                        pD, pI, cntp);
    if (cnt > POOLCAP) {
        exact_tournament(nx, ny, nz, nw, fqx, fqy, fqz, fqw, S,
                         out_idx, out_dist, obase, gbase, lane);
        return;
    }
    // pad to uint4 boundary with MAX keys
    if (lane < 4) pD[cnt + lane] = 0xFFFFFFFFu;
    __syncwarp();
    if (cnt <= 96)       rank_scatter<3>(pD, pI, cnt, out_idx, out_dist, obase, gbase, lane);
    else if (cnt <= 128) rank_scatter<4>(pD, pI, cnt, out_idx, out_dist, obase, gbase, lane);
    else                 rank_scatter<5>(pD, pI, cnt, out_idx, out_dist, obase, gbase, lane);
}

__global__ void __launch_bounds__(THREADS, 2)
knn_fasttau_kernel(const float4* __restrict__ coords,
                   float* __restrict__ out_idx,
                   float* __restrict__ out_dist,
                   int S)
{
    extern __shared__ unsigned char smem_raw[];
    float* nx = reinterpret_cast<float*>(smem_raw);
    float* ny = nx + S;
    float* nz = ny + S;
    float* nw = nz + S;
    int* cntBase = reinterpret_cast<int*>(smem_raw + (size_t)S * 4 * sizeof(float));
    unsigned* poolD = reinterpret_cast<unsigned*>(cntBase + WPB * 2);
    unsigned* poolI = poolD + (size_t)WPB * 2 * PCAP2;

    const int tid  = threadIdx.x;
    const int warp = tid >> 5;
    const int lane = tid & 31;

    const int bps = S / QPB;
    const int seg = blockIdx.x / bps;
    const int qloc = (blockIdx.x % bps) * QPB + warp * 2;   // queries qloc, qloc+1
    const int gbase = seg * S;

    // ---- stage negated SoA coords; zero counters ----
    const float4* segc = coords + (size_t)gbase;
    for (int i = tid; i < S; i += THREADS) {
        float4 c = segc[i];
        nx[i] = -c.x; ny[i] = -c.y; nz[i] = -c.z; nw[i] = -c.w;
    }
    if (tid < WPB * 2) cntBase[tid] = 0;
    __syncthreads();

    const float qax = -nx[qloc],     qay = -ny[qloc],     qaz = -nz[qloc],     qaw = -nw[qloc];
    const float qbx = -nx[qloc + 1], qby = -ny[qloc + 1], qbz = -nz[qloc + 1], qbw = -nw[qloc + 1];

    u64 qAx, qAy, qAz, qAw, qBx, qBy, qBz, qBw;
    PACK2(qAx, qax, qax); PACK2(qAy, qay, qay); PACK2(qAz, qaz, qaz); PACK2(qAw, qaw, qaw);
    PACK2(qBx, qbx, qbx); PACK2(qBy, qby, qby); PACK2(qBz, qbz, qbz); PACK2(qBw, qbw, qbw);

    const int iters = S >> 7;               // 32 iters, 4 candidates/lane/iter
    const int lane4 = lane << 2;

    // ---- prefix pass (8 iters = 1024 candidates): INS2 trackers ----
    unsigned A00 = ~0u, A01 = ~0u, A10 = ~0u, A11 = ~0u;
    unsigned B00 = ~0u, B01 = ~0u, B10 = ~0u, B11 = ~0u;
#pragma unroll 2
    for (int m = 0; m < 8; m++) {
        const int j = (m << 7) + lane4;
        ulonglong2 cx = *reinterpret_cast<const ulonglong2*>(nx + j);
        ulonglong2 cy = *reinterpret_cast<const ulonglong2*>(ny + j);
        ulonglong2 cz = *reinterpret_cast<const ulonglong2*>(nz + j);
        ulonglong2 cw = *reinterpret_cast<const ulonglong2*>(nw + j);
        u64 dA0, dA1, dB0, dB1;
        DIST2(dA0, cx.x, cy.x, cz.x, cw.x, qAx, qAy, qAz, qAw);
        DIST2(dA1, cx.y, cy.y, cz.y, cw.y, qAx, qAy, qAz, qAw);
        DIST2(dB0, cx.x, cy.x, cz.x, cw.x, qBx, qBy, qBz, qBw);
        DIST2(dB1, cx.y, cy.y, cz.y, cw.y, qBx, qBy, qBz, qBw);
        INS2(A00, A01, (unsigned)dA0, (unsigned)(dA0 >> 32));
        INS2(A10, A11, (unsigned)dA1, (unsigned)(dA1 >> 32));
        INS2(B00, B01, (unsigned)dB0, (unsigned)(dB0 >> 32));
        INS2(B10, B11, (unsigned)dB1, (unsigned)(dB1 >> 32));
    }

    // tau0 = (~rank-28 of the 128 collected prefix values): heuristic target
    // of ~112 pool entries in the full set. Validity checked post-hoc.
    unsigned loA = __reduce_min_sync(FULLMASK, umin_(A00, A10));
    unsigned hiA = __reduce_max_sync(FULLMASK, umax_(A00, A10)) + 1u;  // cnt>=63
    unsigned loB = __reduce_min_sync(FULLMASK, umin_(B00, B10));
    unsigned hiB = __reduce_max_sync(FULLMASK, umax_(B00, B10)) + 1u;
    const unsigned tauA = bisect4(A00, A01, A10, A11, loA, hiA, 28u, 12);
    const unsigned tauB = bisect4(B00, B01, B10, B11, loB, hiB, 28u, 12);

    // ---- single main pass: filter + append for both queries ----
    unsigned* pDA = poolD + (size_t)(warp * 2) * PCAP2;
    unsigned* pDB = pDA + PCAP2;
    unsigned* pIA = poolI + (size_t)(warp * 2) * PCAP2;
    unsigned* pIB = pIA + PCAP2;
    int* cntA = cntBase + warp * 2;
    int* cntB = cntA + 1;

#pragma unroll 2
    for (int m = 0; m < iters; m++) {
        const int j = (m << 7) + lane4;
        ulonglong2 cx = *reinterpret_cast<const ulonglong2*>(nx + j);
        ulonglong2 cy = *reinterpret_cast<const ulonglong2*>(ny + j);
        ulonglong2 cz = *reinterpret_cast<const ulonglong2*>(nz + j);
        ulonglong2 cw = *reinterpret_cast<const ulonglong2*>(nw + j);
        u64 dA0, dA1, dB0, dB1;
        DIST2(dA0, cx.x, cy.x, cz.x, cw.x, qAx, qAy, qAz, qAw);
        DIST2(dA1, cx.y, cy.y, cz.y, cw.y, qAx, qAy, qAz, qAw);
        DIST2(dB0, cx.x, cy.x, cz.x, cw.x, qBx, qBy, qBz, qBw);
        DIST2(dB1, cx.y, cy.y, cz.y, cw.y, qBx, qBy, qBz, qBw);

        unsigned a0 = (unsigned)dA0, a1 = (unsigned)(dA0 >> 32);
        unsigned a2 = (unsigned)dA1, a3 = (unsigned)(dA1 >> 32);
        unsigned b0 = (unsigned)dB0, b1 = (unsigned)(dB0 >> 32);
        unsigned b2 = (unsigned)dB1, b3 = (unsigned)(dB1 >> 32);

        if (a0 < tauA) { int p = atomicAdd(cntA, 1);
            if (p < POOLCAP) { pDA[p] = a0; pIA[p] = (unsigned)(j + 0); } }
        if (a1 < tauA) { int p = atomicAdd(cntA, 1);
            if (p < POOLCAP) { pDA[p] = a1; pIA[p] = (unsigned)(j + 1); } }
        if (a2 < tauA) { int p = atomicAdd(cntA, 1);
            if (p < POOLCAP) { pDA[p] = a2; pIA[p] = (unsigned)(j + 2); } }
        if (a3 < tauA) { int p = atomicAdd(cntA, 1);
            if (p < POOLCAP) { pDA[p] = a3; pIA[p] = (unsigned)(j + 3); } }
        if (b0 < tauB) { int p = atomicAdd(cntB, 1);
            if (p < POOLCAP) { pDB[p] = b0; pIB[p] = (unsigned)(j + 0); } }
        if (b1 < tauB) { int p = atomicAdd(cntB, 1);
            if (p < POOLCAP) { pDB[p] = b1; pIB[p] = (unsigned)(j + 1); } }
        if (b2 < tauB) { int p = atomicAdd(cntB, 1);
            if (p < POOLCAP) { pDB[p] = b2; pIB[p] = (unsigned)(j + 2); } }
        if (b3 < tauB) { int p = atomicAdd(cntB, 1);
            if (p < POOLCAP) { pDB[p] = b3; pIB[p] = (unsigned)(j + 3); } }
    }
    __syncwarp();

    const int cA = *cntA;
    const int cB = *cntB;

    const size_t obA = (size_t)(gbase + qloc) * KNN;
    const size_t obB = obA + KNN;

    finish_query(nx, ny, nz, nw, qAx, qAy, qAz, qAw, qax, qay, qaz, qaw,
                 cA, iters, lane4, lane, S, pDA, pIA, cntA,
                 out_idx, out_dist, obA, gbase);
    finish_query(nx, ny, nz, nw, qBx, qBy, qBz, qBw, qbx, qby, qbz, qbw,
                 cB, iters, lane4, lane, S, pDB, pIB, cntB,
                 out_idx, out_dist, obB, gbase);
}

extern "C" void kernel_launch(void* const* d_in, const int* in_sizes, int n_in,
                              void* d_out, int out_size)
{
    // metadata order: K (scalar), coordinates [N*4 f32], row_splits [B+1 i32]
    const float4* coords = (const float4*)d_in[1];
    const int n_coord_floats = in_sizes[1];
    const int B = in_sizes[2] - 1;
    const int N = n_coord_floats / 4;   // D = 4
    const int S = N / B;                // equal-sized segments (4096)

    float* out = (float*)d_out;
    float* out_idx  = out;
    float* out_dist = out + (size_t)N * KNN;

    size_t smem = (size_t)S * 4 * sizeof(float)
                + (size_t)WPB * 2 * sizeof(int)
                + (size_t)WPB * 2 * PCAP2 * 2 * sizeof(unsigned);

    cudaFuncSetAttribute(knn_fasttau_kernel,
                         cudaFuncAttributeMaxDynamicSharedMemorySize, (int)smem);
    cudaFuncSetAttribute(knn_fasttau_kernel,
                         cudaFuncAttributePreferredSharedMemoryCarveout, 100);

    dim3 block(THREADS);
    dim3 grid(N / QPB);
    knn_fasttau_kernel<<<grid, block, smem>>>(coords, out_idx, out_dist, S);
}